// round 1
// baseline (speedup 1.0000x reference)
#include <cuda_runtime.h>
#include <cuda_bf16.h>

#define NUM_CHIPS 4
#define N_EXPERTS 32
#define TOP_K 4
#define SEQ 1024
#define HIDDEN 2048
#define MAX_TOK 1024
#define META_LEN 8
#define NPC (SEQ * TOP_K)          /* 4096 assignments per chip */
#define RANK_THREADS 128
#define CHUNK 32                    /* NPC / RANK_THREADS */

/* scratch (no allocations allowed) */
__device__ int g_counts[NUM_CHIPS * N_EXPERTS];
__device__ int g_chip_off[NUM_CHIPS * N_EXPERTS];
__device__ int g_total[N_EXPERTS];
__device__ int g_rank[NUM_CHIPS * NPC];

/* ------------------------------------------------------------------ */
/* Kernel 1: per-chip histogram + stable within-chip rank.
   One block per chip. Thread t owns assignments [t*32, t*32+32).
   hist layout [expert][thread]: column t accessed only by thread t ->
   bank = t%32, conflict-free in count/assign phases.                  */
__global__ void k_rank(const int* __restrict__ indices) {
    const int c = blockIdx.x;
    const int t = threadIdx.x;
    __shared__ int hist[N_EXPERTS * RANK_THREADS];

    const int* idx = indices + c * NPC + t * CHUNK;
    int e_loc[CHUNK];
#pragma unroll 8
    for (int i = 0; i < CHUNK; i++) e_loc[i] = idx[i];

#pragma unroll
    for (int e = 0; e < N_EXPERTS; e++) hist[e * RANK_THREADS + t] = 0;
    /* each thread only touches its own column before the sync */
#pragma unroll 8
    for (int i = 0; i < CHUNK; i++) hist[e_loc[i] * RANK_THREADS + t]++;
    __syncthreads();

    /* exclusive prefix across chunks, one thread per expert */
    if (t < N_EXPERTS) {
        int sum = 0;
        for (int j = 0; j < RANK_THREADS; j++) {
            int v = hist[t * RANK_THREADS + j];
            hist[t * RANK_THREADS + j] = sum;
            sum += v;
        }
        g_counts[c * N_EXPERTS + t] = sum;
    }
    __syncthreads();

    /* stable rank: walk the chunk in order, bump private column counters */
    const int base = c * NPC + t * CHUNK;
#pragma unroll 8
    for (int i = 0; i < CHUNK; i++) {
        int e = e_loc[i];
        int r = hist[e * RANK_THREADS + t]++;
        g_rank[base + i] = r;
    }
}

/* ------------------------------------------------------------------ */
/* Kernel 2: cross-chip exclusive cumsum -> chip offsets, totals,
   and the experts_counter output section.                             */
__global__ void k_offsets(float* __restrict__ out_cnt) {
    const int e = threadIdx.x;  /* 32 threads */
    int off = 0;
#pragma unroll
    for (int c = 0; c < NUM_CHIPS; c++) {
        g_chip_off[c * N_EXPERTS + e] = off;
        off += g_counts[c * N_EXPERTS + e];
    }
    g_total[e] = off;
    out_cnt[e] = (float)off;    /* counters laid out expert-major == (4,8) row-major */
}

/* ------------------------------------------------------------------ */
/* Kernel 3: zero only the unfilled tail rows (filled rows are written
   by k_scatter; d_out is poisoned so every row needs exactly one writer). */
__global__ void k_zero(float* __restrict__ buf, float* __restrict__ meta) {
    const int row = blockIdx.x;           /* 0 .. 32767 : e*1024 + r */
    const int e = row >> 10;
    const int r = row & (MAX_TOK - 1);
    if (r < g_total[e]) return;

    float4* dst = (float4*)(buf + (size_t)row * HIDDEN);
    const float4 z = make_float4(0.f, 0.f, 0.f, 0.f);
#pragma unroll
    for (int i = threadIdx.x; i < HIDDEN / 4; i += 256) dst[i] = z;
    if (threadIdx.x < META_LEN) meta[(size_t)row * META_LEN + threadIdx.x] = -1.0f;
}

/* ------------------------------------------------------------------ */
/* Kernel 4: one block per assignment — copy the token row + meta row. */
__global__ void k_scatter(const float* __restrict__ x,
                          const float* __restrict__ w,
                          const int* __restrict__ indices,
                          float* __restrict__ buf,
                          float* __restrict__ meta) {
    const int a = blockIdx.x;             /* 0 .. 16383 */
    const int c = a >> 12;                /* / 4096 */
    const int n = a & (NPC - 1);
    const int tok = n >> 2;
    const int k = n & (TOP_K - 1);
    const int e = indices[a];
    const int row = e * MAX_TOK + g_chip_off[c * N_EXPERTS + e] + g_rank[a];

    const float4* src = (const float4*)(x + (size_t)(c * SEQ + tok) * HIDDEN);
    float4* dst = (float4*)(buf + (size_t)row * HIDDEN);
#pragma unroll
    for (int i = threadIdx.x; i < HIDDEN / 4; i += 256) dst[i] = src[i];

    if (threadIdx.x == 0) {
        float* m = meta + (size_t)row * META_LEN;
        m[0] = (float)c;
        m[1] = (float)tok;
        m[2] = (float)k;
        m[3] = (float)e;
        __nv_bfloat16 wb = __float2bfloat16(w[a]);     /* RNE, matches jnp astype */
        short bits = __bfloat16_as_short(wb);
        m[4] = (float)(int)bits;                        /* sign-extended int16->int32 */
        m[5] = 0.f; m[6] = 0.f; m[7] = 0.f;
    }
}

/* ------------------------------------------------------------------ */
extern "C" void kernel_launch(void* const* d_in, const int* in_sizes, int n_in,
                              void* d_out, int out_size) {
    const float* x   = (const float*)d_in[0];
    const float* w   = (const float*)d_in[1];
    const int*   idx = (const int*)d_in[2];

    float* out  = (float*)d_out;
    float* buf  = out;                                                   /* 32*1024*2048 */
    float* meta = out + (size_t)N_EXPERTS * MAX_TOK * HIDDEN;            /* 32*1024*8    */
    float* cnt  = meta + (size_t)N_EXPERTS * MAX_TOK * META_LEN;         /* 32           */

    k_rank<<<NUM_CHIPS, RANK_THREADS>>>(idx);
    k_offsets<<<1, N_EXPERTS>>>(cnt);
    k_zero<<<N_EXPERTS * MAX_TOK, 256>>>(buf, meta);
    k_scatter<<<NUM_CHIPS * NPC, 256>>>(x, w, idx, buf, meta);
}